// round 15
// baseline (speedup 1.0000x reference)
#include <cuda_runtime.h>
#include <cuda_fp16.h>
#include <math.h>
#include <stdint.h>

#define BB 2
#define LL 1024
#define HH 8
#define DD 64
#define SS 10
#define T2 20      // 2S
#define RR 128
#define KTOT 1280  // DD*T2
#define KC 64      // K per chunk
#define NCH 20     // KTOT/KC
#define MT 64      // M tile (l) per CTA

#define TSZA 8192            // 64x64 fp16 tile (128B rows, SW128)
#define TSZB 16384           // 128x64 fp16 tile
#define OFF_AQ 0
#define OFF_AK (1*TSZA)
#define OFF_B  (2*TSZA)
#define BUFSZ (2*TSZA + TSZB)     // 32 KB
#define OFF_QT (2*BUFSZ)          // qtile fp32 16 KB
#define OFF_KT (2*BUFSZ + 16384)  // ktile fp32 16 KB
#define SMEM_BYTES (2*BUFSZ + 2*16384 + 1024)   // ~97 KB

#define ZSCALE 64.0f
#define ZUNSCALE (1.0f/64.0f)

#define NANCH (HH*256*NCH*32)     // anchors: [h][l4][ch][pi], l4 = l/4

static __device__ __align__(16) __half g_zT[(size_t)BB*HH*RR*KTOT];   // plain z, scaled
static __device__ __align__(16) float2 g_anchq[NANCH];   // (cos,sin)(tp*l4*4 + off)
static __device__ __align__(16) float2 g_anchk[NANCH];   // (cos,sin)(tp*l4*4)
static __device__ __align__(16) float2 g_rot[HH*NCH*32]; // (cos,sin)(tp)

// ---------------- helpers ----------------
__device__ __forceinline__ uint32_t smem_u32(const void* p) {
    uint32_t a;
    asm("{ .reg .u64 t; cvta.to.shared.u64 t, %1; cvt.u32.u64 %0, t; }" : "=r"(a) : "l"(p));
    return a;
}
__device__ __forceinline__ uint32_t swz(uint32_t b) { return b ^ ((b >> 3) & 0x70); }
__device__ __forceinline__ uint32_t h2(float x, float y) {
    __half2 h = __floats2half2_rn(x, y);
    return *(uint32_t*)&h;
}
__device__ __forceinline__ void ldsm4(uint32_t* r, uint32_t a) {
    asm volatile("ldmatrix.sync.aligned.m8n8.x4.shared.b16 {%0,%1,%2,%3}, [%4];"
        : "=r"(r[0]), "=r"(r[1]), "=r"(r[2]), "=r"(r[3]) : "r"(a));
}
__device__ __forceinline__ void mma16816(float* d, const uint32_t* a, const uint32_t* b) {
    asm volatile(
        "mma.sync.aligned.m16n8k16.row.col.f32.f16.f16.f32 "
        "{%0,%1,%2,%3}, {%4,%5,%6,%7}, {%8,%9}, {%0,%1,%2,%3};"
        : "+f"(d[0]), "+f"(d[1]), "+f"(d[2]), "+f"(d[3])
        : "r"(a[0]), "r"(a[1]), "r"(a[2]), "r"(a[3]), "r"(b[0]), "r"(b[1]));
}
__device__ __forceinline__ void cp16(uint32_t dst, const void* src) {
    asm volatile("cp.async.cg.shared.global [%0], [%1], 16;" :: "r"(dst), "l"(src) : "memory");
}

// ---------------- pre-kernel: transpose AND anchor tables ----------------
__global__ __launch_bounds__(128)
void spe_pre(const float* __restrict__ zg,
             const float* __restrict__ freqs,
             const float* __restrict__ offsets,
             const float* __restrict__ gains) {
    const int bid = blockIdx.x;
    const int tid = threadIdx.x;

    if (bid < 512) {
        // ---- transpose part: dp in [0,32), h in [0,8), b in [0,2) ----
        int dp = bid & 31;
        int h  = (bid >> 5) & 7;
        int b  = bid >> 8;
        __shared__ float sm[2][T2][RR + 1];
        __shared__ float cf[2][T2];
        const float scale = rsqrtf((float)(RR * DD)) * ZSCALE;

        if (tid < 2*T2) {
            int dd = tid / T2, t = tid - dd*T2;
            float x = gains[(h*DD + dp*2 + dd)*SS + (t % SS)];
            cf[dd][t] = (fmaxf(x, 0.0f) + log1pf(expf(-fabsf(x)))) * scale;
        }
        __syncthreads();

        const float* zd = zg + (((size_t)(b*HH + h)*DD + dp*2)*T2)*RR;
        for (int i = tid; i < 2*T2*RR; i += 128) {
            int dd  = i / (T2*RR);
            int rem = i - dd*(T2*RR);
            int t = rem >> 7, r = rem & 127;
            sm[dd][t][r] = zd[i] * cf[dd][t];
        }
        __syncthreads();

        const int r = tid;   // 0..127
        uint32_t pk[20];
        #pragma unroll
        for (int dd = 0; dd < 2; ++dd)
            #pragma unroll
            for (int j = 0; j < 10; ++j)
                pk[dd*10 + j] = h2(sm[dd][2*j][r], sm[dd][2*j + 1][r]);

        size_t ob = ((size_t)(b*HH + h)*RR + r)*KTOT + (size_t)dp*2*T2;
        uint4* dst = (uint4*)(g_zT + ob);
        #pragma unroll
        for (int v = 0; v < 5; ++v)
            dst[v] = make_uint4(pk[4*v], pk[4*v+1], pk[4*v+2], pk[4*v+3]);
    } else {
        // ---- anchor part ----
        int idx = (bid - 512)*128 + tid;   // < NANCH
        int pi = idx & 31;
        int ch = (idx >> 5) % NCH;
        int l4 = (idx / (32*NCH)) & 255;
        int h  = idx / (32*NCH*256);
        int k  = ch*KC + 2*pi;
        int d  = k / T2;
        int s  = (k - d*T2) >> 1;
        int gi = (h*DD + d)*SS + s;
        float f = freqs[gi];
        float tp = 6.28318530717958647692f * (0.5f / (1.0f + expf(-f)));
        float ph = tp * (float)(l4*4);
        int ai = ((h*256 + l4)*NCH + ch)*32 + pi;
        float2 ak;
        sincosf(ph, &ak.y, &ak.x);
        g_anchk[ai] = ak;
        float2 aq;
        sincosf(ph + offsets[gi], &aq.y, &aq.x);
        g_anchq[ai] = aq;
        if (l4 == 0) {
            float2 r1;
            sincosf(tp, &r1.y, &r1.x);
            g_rot[(h*NCH + ch)*32 + pi] = r1;
        }
    }
}

// ---------------- main HMMA kernel ----------------
// 512 threads, 16 warps: qk = wid>>3 (0=q,1=k), mi = wid&1, ni = (wid>>1)&3
// warp tile m32 x n32, single output tensor -> 32 accums/thread
__global__ __launch_bounds__(512, 2)
void spe_mma_main(const float* __restrict__ qg,
                  const float* __restrict__ kg,
                  float* __restrict__ out) {
    extern __shared__ char smraw[];
    const uint32_t sb   = smem_u32(smraw);
    const uint32_t tb_u = (sb + 1023) & ~1023u;
    char* tb = smraw + (tb_u - sb);

    const int tid  = threadIdx.x;
    const int wid  = tid >> 5;
    const int lane = tid & 31;
    const int l0   = blockIdx.x * MT;
    const int h    = blockIdx.y;
    const int b    = blockIdx.z;

    const int qk = wid >> 3;        // 0 = qhat, 1 = khat
    const int mi = wid & 1;         // m32 block
    const int ni = (wid >> 1) & 3;  // n32 block

    const __half* zT = g_zT + (size_t)(b*HH + h)*RR*KTOT;

    // ---- stage q/k tiles once (fp32, plain layout [l][d]) ----
    {
        #pragma unroll
        for (int u = 0; u < 2; ++u) {
            int idx = tid + u*512;   // 1024 units of 16B per tensor
            int l = idx >> 4;
            int c = (idx & 15) * 4;
            size_t gsrc = (((size_t)b*LL + l0 + l)*HH + h)*DD + c;
            cp16(tb_u + OFF_QT + (uint32_t)(l*256 + c*4), qg + gsrc);
            cp16(tb_u + OFF_KT + (uint32_t)(l*256 + c*4), kg + gsrc);
        }
    }

    // ---- stageB: cp.async shared B tile (128 r x 64 k) of chunk ch into buffer buf ----
    auto stageB = [&](int ch, int buf) {
        const int k0 = ch * KC;
        const uint32_t bs = tb_u + buf*BUFSZ + OFF_B;
        #pragma unroll
        for (int u = 0; u < 2; ++u) {
            int idx = tid + u*512;           // 1024 units of 8 fp16
            int r   = idx >> 3;
            int kl8 = (idx & 7) * 8;
            cp16(bs + swz((uint32_t)(r*128 + kl8*2)), zT + (size_t)r*KTOT + k0 + kl8);
        }
        asm volatile("cp.async.commit_group;" ::: "memory");
    };

    // ---- A-staging state (thread owns k-pair pi, l-strip of 4) ----
    const int pi  = tid & 31;
    const int lb  = (tid >> 5) * 4;
    const int l4g = blockIdx.x*16 + (tid >> 5);
    float st_cq, st_sq, st_ck, st_sk, st_c1, st_s1;
    int   st_d;

    auto prep = [&](int ch) {
        st_d = (ch*KC + 2*pi) / T2;
        int ai = ((h*256 + l4g)*NCH + ch)*32 + pi;
        float2 aq = g_anchq[ai];
        float2 ak = g_anchk[ai];
        float2 rt = g_rot[(h*NCH + ch)*32 + pi];
        st_cq = aq.x; st_sq = aq.y;
        st_ck = ak.x; st_sk = ak.y;
        st_c1 = rt.x; st_s1 = rt.y;
    };

    // stage 1 l of the prepped chunk into buffer buf
    auto partA = [&](int buf, int i) {
        int l = lb + i;
        float qv = *(const float*)(tb + OFF_QT + (l*64 + st_d)*4);
        float kv = *(const float*)(tb + OFF_KT + (l*64 + st_d)*4);
        char* tile = tb + buf*BUFSZ;
        uint32_t byte = swz((uint32_t)(l*128 + pi*4));
        *(uint32_t*)(tile + OFF_AQ + byte) = h2(st_cq*qv, st_sq*qv);
        *(uint32_t*)(tile + OFF_AK + byte) = h2(st_ck*kv, st_sk*kv);
        float t;
        t = st_cq*st_c1 - st_sq*st_s1; st_sq = st_sq*st_c1 + st_cq*st_s1; st_cq = t;
        t = st_ck*st_c1 - st_sk*st_s1; st_sk = st_sk*st_c1 + st_ck*st_s1; st_ck = t;
    };

    // accumulators: [msub 2][ntile 4][4]  (one output tensor per warp)
    float acc[2][4][4];
    #pragma unroll
    for (int i = 0; i < 2; ++i)
        #pragma unroll
        for (int j = 0; j < 4; ++j)
            #pragma unroll
            for (int c = 0; c < 4; ++c) acc[i][j][c] = 0.0f;

    const uint32_t lanerow = lane & 15;
    const uint32_t lanecol = (uint32_t)(lane >> 4) * 16;
    const uint32_t aoff = qk ? OFF_AK : OFF_AQ;

    // prologue: q/k tiles + B(0) in flight, then stage A(0)
    stageB(0, 0);
    asm volatile("cp.async.wait_group 0;" ::: "memory");
    __syncthreads();
    prep(0);
    partA(0, 0); partA(0, 1); partA(0, 2); partA(0, 3);
    __syncthreads();

    #pragma unroll 1
    for (int ch = 0; ch < NCH; ++ch) {
        const int buf = ch & 1;
        const bool more = (ch + 1 < NCH);
        if (more) { stageB(ch + 1, buf ^ 1); prep(ch + 1); }

        const uint32_t base = tb_u + buf*BUFSZ;
        #pragma unroll
        for (int kk = 0; kk < 4; ++kk) {
            const uint32_t kb = kk * 32;   // 16 elems * 2B
            const uint32_t o0 = swz((ni*32 +  0 + lanerow)*128 + lanecol + kb);
            const uint32_t o1 = swz((ni*32 + 16 + lanerow)*128 + lanecol + kb);
            const uint32_t a0 = swz((mi*32 +  0 + lanerow)*128 + lanecol + kb);
            const uint32_t a1 = swz((mi*32 + 16 + lanerow)*128 + lanecol + kb);
            uint32_t t0[4], t1[4], af[2][4];
            ldsm4(t0, base + OFF_B + o0);
            ldsm4(t1, base + OFF_B + o1);
            ldsm4(af[0], base + aoff + a0);
            ldsm4(af[1], base + aoff + a1);
            uint32_t bf[4][2];
            bf[0][0]=t0[0]; bf[0][1]=t0[2]; bf[1][0]=t0[1]; bf[1][1]=t0[3];
            bf[2][0]=t1[0]; bf[2][1]=t1[2]; bf[3][0]=t1[1]; bf[3][1]=t1[3];
            #pragma unroll
            for (int s = 0; s < 2; ++s)
                #pragma unroll
                for (int j = 0; j < 4; ++j)
                    mma16816(acc[s][j], af[s], bf[j]);
            // interleaved A staging for chunk ch+1 (1 of 4 l's)
            if (more) partA(buf ^ 1, kk);
        }

        asm volatile("cp.async.wait_group 0;" ::: "memory");
        __syncthreads();
    }

    // ---- epilogue ----
    const size_t obase = qk ? (size_t)BB * LL * HH * RR : 0;
    #pragma unroll
    for (int s = 0; s < 2; ++s) {
        int row0 = l0 + mi*32 + s*16 + (lane >> 2);
        #pragma unroll
        for (int j = 0; j < 4; ++j) {
            int col = ni*32 + j*8 + (lane & 3)*2;
            size_t oA = obase + (((size_t)b*LL + row0)*HH + h)*RR + col;
            size_t oB = oA + (size_t)8*HH*RR;   // row0 + 8
            *(float2*)(out + oA) = make_float2(acc[s][j][0]*ZUNSCALE, acc[s][j][1]*ZUNSCALE);
            *(float2*)(out + oB) = make_float2(acc[s][j][2]*ZUNSCALE, acc[s][j][3]*ZUNSCALE);
        }
    }
}

extern "C" void kernel_launch(void* const* d_in, const int* in_sizes, int n_in,
                              void* d_out, int out_size) {
    const float* queries = (const float*)d_in[0];
    const float* keys    = (const float*)d_in[1];
    const float* freqs   = (const float*)d_in[2];
    const float* offsets = (const float*)d_in[3];
    const float* gains   = (const float*)d_in[4];
    const float* z       = (const float*)d_in[5];
    float* out = (float*)d_out;

    cudaFuncSetAttribute(spe_mma_main, cudaFuncAttributeMaxDynamicSharedMemorySize, SMEM_BYTES);

    spe_pre<<<512 + NANCH/128, 128>>>(z, freqs, offsets, gains);
    spe_mma_main<<<dim3(LL/MT, HH, BB), 512, SMEM_BYTES>>>(queries, keys, out);
}

// round 16
// speedup vs baseline: 1.3951x; 1.3951x over previous
#include <cuda_runtime.h>
#include <cuda_fp16.h>
#include <math.h>
#include <stdint.h>

#define BB 2
#define LL 1024
#define HH 8
#define DD 64
#define SS 10
#define T2 20      // 2S
#define RR 128
#define KTOT 1280  // DD*T2
#define KC 64      // K per chunk
#define NCH 20     // KTOT/KC
#define MT 64      // M tile (l) per CTA

#define TSZA 8192            // 64x64 fp16 tile (128B rows, SW128)
#define TSZB 16384           // 128x64 fp16 tile
#define OFF_AQ 0
#define OFF_AK (1*TSZA)
#define OFF_B  (2*TSZA)
#define BUFSZ (2*TSZA + TSZB)     // 32 KB
#define OFF_QT (2*BUFSZ)          // qtile fp32 16 KB
#define OFF_KT (2*BUFSZ + 16384)  // ktile fp32 16 KB
#define SMEM_BYTES (2*BUFSZ + 2*16384 + 1024)   // ~97 KB

#define ZSCALE 64.0f
#define ZUNSCALE (1.0f/64.0f)

#define NANCH (HH*128*NCH*32)     // anchors: [h][l8][ch][pi], l8 = l/8

static __device__ __align__(16) __half g_zT[(size_t)BB*HH*RR*KTOT];   // plain z, scaled
static __device__ __align__(16) float2 g_anchq[NANCH];   // (cos,sin)(tp*l8*8 + off)
static __device__ __align__(16) float2 g_anchk[NANCH];   // (cos,sin)(tp*l8*8)
static __device__ __align__(16) float2 g_rot[HH*NCH*32]; // (cos,sin)(tp)

// ---------------- helpers ----------------
__device__ __forceinline__ uint32_t smem_u32(const void* p) {
    uint32_t a;
    asm("{ .reg .u64 t; cvta.to.shared.u64 t, %1; cvt.u32.u64 %0, t; }" : "=r"(a) : "l"(p));
    return a;
}
__device__ __forceinline__ uint32_t swz(uint32_t b) { return b ^ ((b >> 3) & 0x70); }
__device__ __forceinline__ uint32_t h2(float x, float y) {
    __half2 h = __floats2half2_rn(x, y);
    return *(uint32_t*)&h;
}
__device__ __forceinline__ void ldsm4(uint32_t* r, uint32_t a) {
    asm volatile("ldmatrix.sync.aligned.m8n8.x4.shared.b16 {%0,%1,%2,%3}, [%4];"
        : "=r"(r[0]), "=r"(r[1]), "=r"(r[2]), "=r"(r[3]) : "r"(a));
}
__device__ __forceinline__ void mma16816(float* d, const uint32_t* a, const uint32_t* b) {
    asm volatile(
        "mma.sync.aligned.m16n8k16.row.col.f32.f16.f16.f32 "
        "{%0,%1,%2,%3}, {%4,%5,%6,%7}, {%8,%9}, {%0,%1,%2,%3};"
        : "+f"(d[0]), "+f"(d[1]), "+f"(d[2]), "+f"(d[3])
        : "r"(a[0]), "r"(a[1]), "r"(a[2]), "r"(a[3]), "r"(b[0]), "r"(b[1]));
}
__device__ __forceinline__ void cp16(uint32_t dst, const void* src) {
    asm volatile("cp.async.cg.shared.global [%0], [%1], 16;" :: "r"(dst), "l"(src) : "memory");
}

// ---------------- pre-kernel: transpose AND anchor tables ----------------
__global__ __launch_bounds__(128)
void spe_pre(const float* __restrict__ zg,
             const float* __restrict__ freqs,
             const float* __restrict__ offsets,
             const float* __restrict__ gains) {
    const int bid = blockIdx.x;
    const int tid = threadIdx.x;

    if (bid < 512) {
        // ---- transpose part: dp in [0,32), h in [0,8), b in [0,2) ----
        int dp = bid & 31;
        int h  = (bid >> 5) & 7;
        int b  = bid >> 8;
        __shared__ float sm[2][T2][RR + 1];
        __shared__ float cf[2][T2];
        const float scale = rsqrtf((float)(RR * DD)) * ZSCALE;

        if (tid < 2*T2) {
            int dd = tid / T2, t = tid - dd*T2;
            float x = gains[(h*DD + dp*2 + dd)*SS + (t % SS)];
            cf[dd][t] = (fmaxf(x, 0.0f) + log1pf(expf(-fabsf(x)))) * scale;
        }
        __syncthreads();

        const float* zd = zg + (((size_t)(b*HH + h)*DD + dp*2)*T2)*RR;
        for (int i = tid; i < 2*T2*RR; i += 128) {
            int dd  = i / (T2*RR);
            int rem = i - dd*(T2*RR);
            int t = rem >> 7, r = rem & 127;
            sm[dd][t][r] = zd[i] * cf[dd][t];
        }
        __syncthreads();

        const int r = tid;   // 0..127
        uint32_t pk[20];
        #pragma unroll
        for (int dd = 0; dd < 2; ++dd)
            #pragma unroll
            for (int j = 0; j < 10; ++j)
                pk[dd*10 + j] = h2(sm[dd][2*j][r], sm[dd][2*j + 1][r]);

        size_t ob = ((size_t)(b*HH + h)*RR + r)*KTOT + (size_t)dp*2*T2;
        uint4* dst = (uint4*)(g_zT + ob);
        #pragma unroll
        for (int v = 0; v < 5; ++v)
            dst[v] = make_uint4(pk[4*v], pk[4*v+1], pk[4*v+2], pk[4*v+3]);
    } else {
        // ---- anchor part ----
        int idx = (bid - 512)*128 + tid;   // < NANCH
        int pi = idx & 31;
        int ch = (idx >> 5) % NCH;
        int l8 = (idx / (32*NCH)) & 127;
        int h  = idx / (32*NCH*128);
        int k  = ch*KC + 2*pi;
        int d  = k / T2;
        int s  = (k - d*T2) >> 1;
        int gi = (h*DD + d)*SS + s;
        float f = freqs[gi];
        float tp = 6.28318530717958647692f * (0.5f / (1.0f + expf(-f)));
        float ph = tp * (float)(l8*8);
        int ai = ((h*128 + l8)*NCH + ch)*32 + pi;
        float2 ak;
        sincosf(ph, &ak.y, &ak.x);
        g_anchk[ai] = ak;
        float2 aq;
        sincosf(ph + offsets[gi], &aq.y, &aq.x);
        g_anchq[ai] = aq;
        if (l8 == 0) {
            float2 r1;
            sincosf(tp, &r1.y, &r1.x);
            g_rot[(h*NCH + ch)*32 + pi] = r1;
        }
    }
}

// ---------------- main HMMA kernel ----------------
// 256 threads, 8 warps: mi = wid&1 (m32), ni = wid>>1 (n32); each warp computes
// BOTH q and k accumulators for its m32 x n32 tile (shared B fragments).
__global__ __launch_bounds__(256, 2)
void spe_mma_main(const float* __restrict__ qg,
                  const float* __restrict__ kg,
                  float* __restrict__ out) {
    extern __shared__ char smraw[];
    const uint32_t sb   = smem_u32(smraw);
    const uint32_t tb_u = (sb + 1023) & ~1023u;
    char* tb = smraw + (tb_u - sb);

    const int tid  = threadIdx.x;
    const int wid  = tid >> 5;
    const int lane = tid & 31;
    const int l0   = blockIdx.x * MT;
    const int h    = blockIdx.y;
    const int b    = blockIdx.z;

    const int mi = wid & 1;   // 2 m32 blocks
    const int ni = wid >> 1;  // 4 n32 blocks

    const __half* zT = g_zT + (size_t)(b*HH + h)*RR*KTOT;

    // ---- stage q/k tiles once (fp32, plain layout [l][d]) ----
    #pragma unroll
    for (int u = 0; u < 4; ++u) {
        int idx = tid + u*256;   // 1024 units of 16B per tensor
        int l = idx >> 4;
        int c = (idx & 15) * 4;
        size_t gsrc = (((size_t)b*LL + l0 + l)*HH + h)*DD + c;
        cp16(tb_u + OFF_QT + (uint32_t)(l*256 + c*4), qg + gsrc);
        cp16(tb_u + OFF_KT + (uint32_t)(l*256 + c*4), kg + gsrc);
    }

    // ---- stageB: cp.async shared B tile (128 r x 64 k) of chunk ch into buffer buf ----
    auto stageB = [&](int ch, int buf) {
        const int k0 = ch * KC;
        const uint32_t bs = tb_u + buf*BUFSZ + OFF_B;
        #pragma unroll
        for (int u = 0; u < 4; ++u) {
            int idx = tid + u*256;           // 1024 units of 8 fp16
            int r   = idx >> 3;
            int kl8 = (idx & 7) * 8;
            cp16(bs + swz((uint32_t)(r*128 + kl8*2)), zT + (size_t)r*KTOT + k0 + kl8);
        }
        asm volatile("cp.async.commit_group;" ::: "memory");
    };

    // ---- A-staging state (thread owns k-pair pi, l-strip of 8) ----
    const int pi  = tid & 31;
    const int lb  = (tid >> 5) * 8;
    const int l8g = blockIdx.x*8 + (tid >> 5);
    float st_cq, st_sq, st_ck, st_sk, st_c1, st_s1;
    int   st_d;

    auto prep = [&](int ch) {
        st_d = (ch*KC + 2*pi) / T2;
        int ai = ((h*128 + l8g)*NCH + ch)*32 + pi;
        float2 aq = g_anchq[ai];
        float2 ak = g_anchk[ai];
        float2 rt = g_rot[(h*NCH + ch)*32 + pi];
        st_cq = aq.x; st_sq = aq.y;
        st_ck = ak.x; st_sk = ak.y;
        st_c1 = rt.x; st_s1 = rt.y;
    };

    // stage 2 l's of the prepped chunk into buffer buf
    auto partA = [&](int buf, int i0) {
        char* tile = tb + buf*BUFSZ;
        #pragma unroll
        for (int ii = 0; ii < 2; ++ii) {
            int l = lb + i0 + ii;
            float qv = *(const float*)(tb + OFF_QT + (l*64 + st_d)*4);
            float kv = *(const float*)(tb + OFF_KT + (l*64 + st_d)*4);
            uint32_t byte = swz((uint32_t)(l*128 + pi*4));
            *(uint32_t*)(tile + OFF_AQ + byte) = h2(st_cq*qv, st_sq*qv);
            *(uint32_t*)(tile + OFF_AK + byte) = h2(st_ck*kv, st_sk*kv);
            float t;
            t = st_cq*st_c1 - st_sq*st_s1; st_sq = st_sq*st_c1 + st_cq*st_s1; st_cq = t;
            t = st_ck*st_c1 - st_sk*st_s1; st_sk = st_sk*st_c1 + st_ck*st_s1; st_ck = t;
        }
    };

    // accumulators: [msub 2][ntile 4][4] for q and k
    float accq[2][4][4];
    float acck[2][4][4];
    #pragma unroll
    for (int i = 0; i < 2; ++i)
        #pragma unroll
        for (int j = 0; j < 4; ++j)
            #pragma unroll
            for (int c = 0; c < 4; ++c) { accq[i][j][c] = 0.0f; acck[i][j][c] = 0.0f; }

    const uint32_t lanerow = lane & 15;
    const uint32_t lanecol = (uint32_t)(lane >> 4) * 16;

    // prologue: q/k tiles + B(0) in flight, then stage A(0)
    stageB(0, 0);
    asm volatile("cp.async.wait_group 0;" ::: "memory");
    __syncthreads();
    prep(0);
    partA(0, 0); partA(0, 2); partA(0, 4); partA(0, 6);
    __syncthreads();

    #pragma unroll 1
    for (int ch = 0; ch < NCH; ++ch) {
        const int buf = ch & 1;
        const bool more = (ch + 1 < NCH);
        if (more) { stageB(ch + 1, buf ^ 1); prep(ch + 1); }

        const uint32_t base = tb_u + buf*BUFSZ;
        #pragma unroll
        for (int kk = 0; kk < 4; ++kk) {
            const uint32_t kb = kk * 32;   // 16 elems * 2B
            const uint32_t o0 = swz((ni*32 +  0 + lanerow)*128 + lanecol + kb);
            const uint32_t o1 = swz((ni*32 + 16 + lanerow)*128 + lanecol + kb);
            const uint32_t a0 = swz((mi*32 +  0 + lanerow)*128 + lanecol + kb);
            const uint32_t a1 = swz((mi*32 + 16 + lanerow)*128 + lanecol + kb);
            // shared B fragments + Aq + Ak (6 LDSM total)
            uint32_t t0[4], t1[4];
            ldsm4(t0, base + OFF_B + o0);
            ldsm4(t1, base + OFF_B + o1);
            uint32_t bf[4][2];
            bf[0][0]=t0[0]; bf[0][1]=t0[2]; bf[1][0]=t0[1]; bf[1][1]=t0[3];
            bf[2][0]=t1[0]; bf[2][1]=t1[2]; bf[3][0]=t1[1]; bf[3][1]=t1[3];
            {
                uint32_t aq[2][4];
                ldsm4(aq[0], base + OFF_AQ + a0);
                ldsm4(aq[1], base + OFF_AQ + a1);
                #pragma unroll
                for (int s = 0; s < 2; ++s)
                    #pragma unroll
                    for (int j = 0; j < 4; ++j)
                        mma16816(accq[s][j], aq[s], bf[j]);
            }
            {
                uint32_t ak[2][4];
                ldsm4(ak[0], base + OFF_AK + a0);
                ldsm4(ak[1], base + OFF_AK + a1);
                #pragma unroll
                for (int s = 0; s < 2; ++s)
                    #pragma unroll
                    for (int j = 0; j < 4; ++j)
                        mma16816(acck[s][j], ak[s], bf[j]);
            }
            // interleaved A staging for chunk ch+1 (2 of 8 l's)
            if (more) partA(buf ^ 1, 2*kk);
        }

        asm volatile("cp.async.wait_group 0;" ::: "memory");
        __syncthreads();
    }

    // ---- epilogue (undo ZSCALE) ----
    const size_t khat_off = (size_t)BB * LL * HH * RR;
    #pragma unroll
    for (int s = 0; s < 2; ++s) {
        int row0 = l0 + mi*32 + s*16 + (lane >> 2);
        #pragma unroll
        for (int j = 0; j < 4; ++j) {
            int col = ni*32 + j*8 + (lane & 3)*2;
            size_t oA = (((size_t)b*LL + row0)*HH + h)*RR + col;
            size_t oB = oA + (size_t)8*HH*RR;   // row0 + 8
            *(float2*)(out + oA) = make_float2(accq[s][j][0]*ZUNSCALE, accq[s][j][1]*ZUNSCALE);
            *(float2*)(out + oB) = make_float2(accq[s][j][2]*ZUNSCALE, accq[s][j][3]*ZUNSCALE);
            *(float2*)(out + khat_off + oA) = make_float2(acck[s][j][0]*ZUNSCALE, acck[s][j][1]*ZUNSCALE);
            *(float2*)(out + khat_off + oB) = make_float2(acck[s][j][2]*ZUNSCALE, acck[s][j][3]*ZUNSCALE);
        }
    }
}

extern "C" void kernel_launch(void* const* d_in, const int* in_sizes, int n_in,
                              void* d_out, int out_size) {
    const float* queries = (const float*)d_in[0];
    const float* keys    = (const float*)d_in[1];
    const float* freqs   = (const float*)d_in[2];
    const float* offsets = (const float*)d_in[3];
    const float* gains   = (const float*)d_in[4];
    const float* z       = (const float*)d_in[5];
    float* out = (float*)d_out;

    cudaFuncSetAttribute(spe_mma_main, cudaFuncAttributeMaxDynamicSharedMemorySize, SMEM_BYTES);

    spe_pre<<<512 + NANCH/128, 128>>>(z, freqs, offsets, gains);
    spe_mma_main<<<dim3(LL/MT, HH, BB), 256, SMEM_BYTES>>>(queries, keys, out);
}